// round 1
// baseline (speedup 1.0000x reference)
#include <cuda_runtime.h>

// QuantumLikeLayer: out[b, :] = CZ_diag * (H_full @ in[b, :])
// H_full = H^{\otimes 11}  -> fast Walsh-Hadamard transform, N = 2048.
// Scale 2^{-5.5} folded to the end; CZ sign = -1 iff output index bits 10&9 set.

#define NQUBITS 11
#define NN 2048

static __device__ __forceinline__ void reg_butterfly8(float v[8]) {
    // 3 butterfly stages over the 3 "register" bits of k (0..7)
#pragma unroll
    for (int m = 1; m < 8; m <<= 1) {
#pragma unroll
        for (int k = 0; k < 8; k++) {
            if (!(k & m)) {
                float a = v[k];
                float b = v[k | m];
                v[k]     = a + b;
                v[k | m] = a - b;
            }
        }
    }
}

__global__ void __launch_bounds__(256, 8)
fwht_cz_kernel(const float* __restrict__ in, float* __restrict__ out, int rows) {
    __shared__ float s[NN];

    const int row = blockIdx.x;
    if (row >= rows) return;

    const float* __restrict__ rp = in  + (size_t)row * NN;
    float* __restrict__       op = out + (size_t)row * NN;

    const int t    = threadIdx.x;      // 0..255
    const int lane = t & 31;
    const int warp = t >> 5;           // 0..7

    // ---- load, layout A: element index i = t + 256*k  (k = reg slot) ----
    // per k, a warp reads 32 consecutive floats -> 128B coalesced
    float v[8];
#pragma unroll
    for (int k = 0; k < 8; k++) v[k] = rp[t + 256 * k];

    // ---- stages for bits 8..10 (the k bits in layout A): registers ----
    reg_butterfly8(v);

    // ---- stages for bits 0..4 (the lane bits): warp shuffles ----
#pragma unroll
    for (int m = 1; m <= 16; m <<= 1) {
#pragma unroll
        for (int k = 0; k < 8; k++) {
            float p = __shfl_xor_sync(0xffffffffu, v[k], m);
            v[k] = (lane & m) ? (p - v[k]) : (v[k] + p);
        }
    }

    // ---- one smem exchange: layout A -> layout B: i = lane + 32*k + 256*warp ----
    // write: consecutive lanes -> consecutive addresses (conflict-free)
#pragma unroll
    for (int k = 0; k < 8; k++) s[t + 256 * k] = v[k];
    __syncthreads();
    // read: consecutive lanes -> consecutive addresses (conflict-free)
#pragma unroll
    for (int k = 0; k < 8; k++) v[k] = s[lane + 32 * k + 256 * warp];

    // ---- stages for bits 5..7 (the k bits in layout B): registers ----
    reg_butterfly8(v);

    // ---- CZ sign + normalization, then store ----
    // In layout B, bits 8..10 of i equal `warp` exactly (lane + 32k <= 255),
    // so sign is uniform per warp: negative iff bits 10 and 9 set <=> warp >= 6.
    const float SCALE = 0.022097086912079608f;   // 2^{-5.5}
    const float sc = (warp >= 6) ? -SCALE : SCALE;
#pragma unroll
    for (int k = 0; k < 8; k++) {
        op[lane + 32 * k + 256 * warp] = v[k] * sc;   // 128B coalesced per (warp,k)
    }
}

extern "C" void kernel_launch(void* const* d_in, const int* in_sizes, int n_in,
                              void* d_out, int out_size) {
    const float* in = (const float*)d_in[0];
    float* out = (float*)d_out;
    const int rows = in_sizes[0] / NN;   // 16384
    fwht_cz_kernel<<<rows, 256>>>(in, out, rows);
}

// round 2
// speedup vs baseline: 1.0914x; 1.0914x over previous
#include <cuda_runtime.h>

// QuantumLikeLayer: out[b, :] = CZ_diag * (H^{⊗11} @ in[b, :]), N = 2048.
// Fast Walsh-Hadamard transform, fully 128-bit vectorized:
//   - load  layout: i = 512j + 4t + c   (regs carry bits 0,1,9,10)
//   - 4 register butterfly stages (bits 0,1,9,10)
//   - 5 shuffle stages (bits 2..6 = lane bits)
//   - one float4 smem exchange -> regs carry bits 7,8 (+ bits 0,1 for IO)
//   - 2 register butterfly stages (bits 7,8)
//   - store layout: i = c + (lane<<2) + (w<<7) + (warp<<9); CZ sign uniform/warp

#define NN 2048

__global__ void __launch_bounds__(128)
fwht_cz_kernel(const float4* __restrict__ in, float4* __restrict__ out) {
    __shared__ float4 s4[NN / 4];   // 8 KB

    const int row  = blockIdx.x;
    const int t    = threadIdx.x;   // 0..127
    const int lane = t & 31;
    const int warp = t >> 5;        // 0..3

    const float4* __restrict__ ip = in  + (size_t)row * (NN / 4);
    float4* __restrict__       op = out + (size_t)row * (NN / 4);

    // ---- load: 4x LDG.128, reg r = c + 4j holds i = 512j + 4t + c ----
    float v[16];
#pragma unroll
    for (int j = 0; j < 4; j++) {
        float4 q = ip[128 * j + t];
        v[4 * j + 0] = q.x;
        v[4 * j + 1] = q.y;
        v[4 * j + 2] = q.z;
        v[4 * j + 3] = q.w;
    }

    // ---- register stages for bits 0,1 (m=1,2) and 9,10 (m=4,8) ----
#pragma unroll
    for (int m = 1; m < 16; m <<= 1) {
#pragma unroll
        for (int r = 0; r < 16; r++) {
            if (!(r & m)) {
                float a = v[r], b = v[r | m];
                v[r]     = a + b;
                v[r | m] = a - b;
            }
        }
    }

    // ---- shuffle stages for bits 2..6 (lane bits) ----
#pragma unroll
    for (int m = 1; m <= 16; m <<= 1) {
#pragma unroll
        for (int r = 0; r < 16; r++) {
            float p = __shfl_xor_sync(0xffffffffu, v[r], m);
            v[r] = (lane & m) ? (p - v[r]) : (v[r] + p);
        }
    }

    // ---- float4 smem exchange: bring bits 7,8 (warp bits of t) into regs ----
    // write layout A: float4 index = i>>2 = 128j + t   (conflict-free)
#pragma unroll
    for (int j = 0; j < 4; j++)
        s4[128 * j + t] = make_float4(v[4 * j], v[4 * j + 1], v[4 * j + 2], v[4 * j + 3]);
    __syncthreads();
    // read layout B: reg r = c + 4w holds i = c + (lane<<2) + (w<<7) + (warp<<9)
    // float4 index = lane + 32w + 128*warp   (conflict-free)
#pragma unroll
    for (int w = 0; w < 4; w++) {
        float4 q = s4[lane + 32 * w + 128 * warp];
        v[4 * w + 0] = q.x;
        v[4 * w + 1] = q.y;
        v[4 * w + 2] = q.z;
        v[4 * w + 3] = q.w;
    }

    // ---- register stages for bits 7,8 (m=4,8 over reg index) ----
#pragma unroll
    for (int m = 4; m <= 8; m <<= 1) {
#pragma unroll
        for (int r = 0; r < 16; r++) {
            if (!(r & m)) {
                float a = v[r], b = v[r | m];
                v[r]     = a + b;
                v[r | m] = a - b;
            }
        }
    }

    // ---- CZ sign + scale, 4x STG.128 ----
    // output i bits 9,10 == warp; negative iff both set <=> warp == 3
    const float S  = 0.022097086912079608f;   // 2^{-5.5}
    const float sc = (warp == 3) ? -S : S;
#pragma unroll
    for (int w = 0; w < 4; w++) {
        op[lane + 32 * w + 128 * warp] =
            make_float4(v[4 * w] * sc, v[4 * w + 1] * sc,
                        v[4 * w + 2] * sc, v[4 * w + 3] * sc);
    }
}

extern "C" void kernel_launch(void* const* d_in, const int* in_sizes, int n_in,
                              void* d_out, int out_size) {
    const float4* in = (const float4*)d_in[0];
    float4* out = (float4*)d_out;
    const int rows = in_sizes[0] / NN;   // 16384
    fwht_cz_kernel<<<rows, 128>>>(in, out);
}

// round 3
// speedup vs baseline: 1.1926x; 1.0928x over previous
#include <cuda_runtime.h>

// QuantumLikeLayer: out[b,:] = CZ_diag * (H^{⊗11} @ in[b,:]), N=2048, FWHT.
// One warp per row. 64 elems/thread as 32 packed f32x2 registers.
// Stage plan (element-index bits i0..i10):
//   load (coalesced float4) + i0 butterfly scalar at load
//   P1: i1,i7..i10 in registers (packed f32x2)
//   exch1 (smem, XOR-swizzled, conflict-free) -> regs carry i2..i5
//   P2: i2..i5 in registers
//   i6: single shuffle stage (shfl_xor 1 + packed fma with ±1)
//   CZ sign + 2^-5.5 scale: thread-uniform packed multiply
//   exch2 (smem) -> final coalesced layout, STG.128

#define NN 2048
typedef unsigned long long u64;

__device__ __forceinline__ u64 pk(float x, float y) {
    u64 d; asm("mov.b64 %0,{%1,%2};" : "=l"(d) : "f"(x), "f"(y)); return d;
}
__device__ __forceinline__ void upk(u64 v, float& x, float& y) {
    asm("mov.b64 {%0,%1},%2;" : "=f"(x), "=f"(y) : "l"(v));
}
__device__ __forceinline__ u64 padd(u64 a, u64 b) {
    u64 d; asm("add.rn.f32x2 %0,%1,%2;" : "=l"(d) : "l"(a), "l"(b)); return d;
}
__device__ __forceinline__ u64 pfma(u64 a, u64 b, u64 c) {
    u64 d; asm("fma.rn.f32x2 %0,%1,%2,%3;" : "=l"(d) : "l"(a), "l"(b), "l"(c)); return d;
}
__device__ __forceinline__ u64 pmul(u64 a, u64 b) {
    u64 d; asm("mul.rn.f32x2 %0,%1,%2;" : "=l"(d) : "l"(a), "l"(b)); return d;
}

// butterfly over packed regs: pairs (r, r|M): (a+b, a-b); a-b via fma(b,-1,a)
template <int M>
__device__ __forceinline__ void bfly(u64 v[32], u64 NEG1) {
#pragma unroll
    for (int r = 0; r < 32; r++) {
        if (!(r & M)) {
            u64 a = v[r], b = v[r | M];
            v[r]     = padd(a, b);
            v[r | M] = pfma(b, NEG1, a);
        }
    }
}

__global__ void __launch_bounds__(128, 4)
fwht_cz_kernel(const float4* __restrict__ in, float4* __restrict__ out) {
    __shared__ float4 s4[4][512];   // 8KB per warp, 32KB per CTA

    const int lane = threadIdx.x & 31;
    const int wid  = threadIdx.x >> 5;
    const int row  = (blockIdx.x << 2) + wid;   // one warp per row

    const float4* __restrict__ ip = in  + (size_t)row * (NN / 4);
    float4* __restrict__       op = out + (size_t)row * (NN / 4);
    float4* sw = s4[wid];

    const u64 NEG1 = pk(-1.0f, -1.0f);
    u64 v[32];

    // ---- load (layout A: pair p = p0 + 2*lane + 64*j; p bits = i1..i10) ----
    // float4 f-index = lane + 32*j, fully coalesced. Fuse i0 butterfly.
#pragma unroll
    for (int j = 0; j < 16; j++) {
        float4 q = ip[lane + 32 * j];
        v[2 * j]     = pk(q.x + q.y, q.x - q.y);
        v[2 * j + 1] = pk(q.z + q.w, q.z - q.w);
    }

    // ---- P1: i1 (reg bit 0), i7..i10 (reg bits 1..4) ----
    bfly<1>(v, NEG1); bfly<2>(v, NEG1); bfly<4>(v, NEG1);
    bfly<8>(v, NEG1); bfly<16>(v, NEG1);

    // ---- exch1 write (layout A): f = lane + 32j, swizzled ----
    const int h = lane >> 4;
#pragma unroll
    for (int j = 0; j < 16; j++) {
        int e = (h + 2 * j) & 7;
        int f = (lane ^ e) + 32 * j;
        float a, b, c, d;
        upk(v[2 * j], a, b); upk(v[2 * j + 1], c, d);
        sw[f] = make_float4(a, b, c, d);
    }
    __syncwarp();

    // ---- exch1 read (layout B): f = k + 16*lane; regs now carry i2..i5 ----
    const int m7   = lane & 7;
    const int base = 16 * lane;
#pragma unroll
    for (int k = 0; k < 16; k++) {
        float4 q = sw[base + (k ^ m7)];
        v[2 * k]     = pk(q.x, q.y);
        v[2 * k + 1] = pk(q.z, q.w);
    }

    // ---- P2: i2..i5 (reg bits 1..4) ----
    bfly<2>(v, NEG1); bfly<4>(v, NEG1);
    bfly<8>(v, NEG1); bfly<16>(v, NEG1);

    // ---- i6: lane bit 0 in layout B; one shuffle stage ----
    {
        float s = (lane & 1) ? -1.0f : 1.0f;
        u64 s2 = pk(s, s);
#pragma unroll
        for (int r = 0; r < 32; r++) {
            u64 p = __shfl_xor_sync(0xffffffffu, v[r], 1);
            v[r] = pfma(v[r], s2, p);   // (lane&1)? p - v : v + p
        }
    }

    // ---- CZ sign + 2^{-5.5}: i9,i10 = lane bits 3,4 -> thread-uniform ----
    {
        const float S  = 0.022097086912079608f;   // 2^{-5.5}
        float sc = ((lane & 24) == 24) ? -S : S;
        u64 sc2 = pk(sc, sc);
#pragma unroll
        for (int r = 0; r < 32; r++) v[r] = pmul(v[r], sc2);
    }

    // ---- exch2 write (layout B indexing; same per-thread slots as exch1 read) ----
#pragma unroll
    for (int k = 0; k < 16; k++) {
        float a, b, c, d;
        upk(v[2 * k], a, b); upk(v[2 * k + 1], c, d);
        sw[base + (k ^ m7)] = make_float4(a, b, c, d);
    }
    __syncwarp();

    // ---- exch2 read (layout C = final) + coalesced STG.128 ----
#pragma unroll
    for (int j = 0; j < 16; j++) {
        int e = (h + 2 * j) & 7;
        int f = (lane ^ e) + 32 * j;
        op[lane + 32 * j] = sw[f];
    }
}

extern "C" void kernel_launch(void* const* d_in, const int* in_sizes, int n_in,
                              void* d_out, int out_size) {
    const float4* in = (const float4*)d_in[0];
    float4* out = (float4*)d_out;
    const int rows = in_sizes[0] / NN;    // 16384
    fwht_cz_kernel<<<rows / 4, 128>>>(in, out);
}

// round 4
// speedup vs baseline: 1.1943x; 1.0014x over previous
#include <cuda_runtime.h>

// QuantumLikeLayer: out[b,:] = CZ_diag * (H^{⊗11} @ in[b,:]), N=2048, FWHT.
// One warp per row, 64 elems/thread as 32 packed f32x2 regs. ZERO shuffles.
//   load  (coalesced): regs carry i0 (pack), i1, i7..i10  -> 6 reg stages
//   exch1 (smem, 8B write / 16B read, XOR swizzle): regs carry i0, i2..i6
//   P2: 5 reg stages (i2..i6); CZ sign + 2^-5.5 thread-uniform
//   exch2 (inverse of exch1) -> coalesced STG.128

#define NN 2048
typedef unsigned long long u64;

__device__ __forceinline__ u64 pk(float x, float y) {
    u64 d; asm("mov.b64 %0,{%1,%2};" : "=l"(d) : "f"(x), "f"(y)); return d;
}
__device__ __forceinline__ void upk(u64 v, float& x, float& y) {
    asm("mov.b64 {%0,%1},%2;" : "=f"(x), "=f"(y) : "l"(v));
}
__device__ __forceinline__ u64 padd(u64 a, u64 b) {
    u64 d; asm("add.rn.f32x2 %0,%1,%2;" : "=l"(d) : "l"(a), "l"(b)); return d;
}
__device__ __forceinline__ u64 pfma(u64 a, u64 b, u64 c) {
    u64 d; asm("fma.rn.f32x2 %0,%1,%2,%3;" : "=l"(d) : "l"(a), "l"(b), "l"(c)); return d;
}
__device__ __forceinline__ u64 pmul(u64 a, u64 b) {
    u64 d; asm("mul.rn.f32x2 %0,%1,%2;" : "=l"(d) : "l"(a), "l"(b)); return d;
}

template <int M>
__device__ __forceinline__ void bfly(u64 v[32], u64 NEG1) {
#pragma unroll
    for (int r = 0; r < 32; r++) {
        if (!(r & M)) {
            u64 a = v[r], b = v[r | M];
            v[r]     = padd(a, b);
            v[r | M] = pfma(b, NEG1, a);   // a - b
        }
    }
}

__global__ void __launch_bounds__(128, 4)
fwht_cz_kernel(const float4* __restrict__ in, float4* __restrict__ out) {
    // smem layout per warp (8KB, viewed as 512 float4 / 1024 u64):
    //   unit (r, col, h): u64 index = 32*r + 2*(col ^ (r&15)) + h
    //   r   = i1 + 2*i7 + 4*i8 + 8*i9 + 16*i10   (5 bits, "row", 256B region)
    //   col = i3..i6 (4 bits), h = i2, u64 holds the i0 pair
    __shared__ u64 sm[4][1024];

    const int lane = threadIdx.x & 31;
    const int wid  = threadIdx.x >> 5;
    const int row  = (blockIdx.x << 2) + wid;

    const float4* __restrict__ ip = in  + (size_t)row * (NN / 4);
    float4* __restrict__       op = out + (size_t)row * (NN / 4);
    u64* sw = sm[wid];

    const u64 NEG1 = pk(-1.0f, -1.0f);
    u64 v[32];

    // ---- load (f = lane + 32j; lane = i2..i6, j = i7..i10, float4 = i0,i1) ----
    // fuse i0 stage; pack slot = i0; reg r = i1 + 2*j
#pragma unroll
    for (int j = 0; j < 16; j++) {
        float4 q = ip[lane + 32 * j];
        v[2 * j]     = pk(q.x + q.y, q.x - q.y);   // i1 = 0
        v[2 * j + 1] = pk(q.z + q.w, q.z - q.w);   // i1 = 1
    }

    // ---- P1: i1 (bit0), i7..i10 (bits 1..4) ----
    bfly<1>(v, NEG1); bfly<2>(v, NEG1); bfly<4>(v, NEG1);
    bfly<8>(v, NEG1); bfly<16>(v, NEG1);

    // ---- exch1 write: STS.64; thread lane = i2..i6 (col = lane>>1, h = lane&1) ----
    const int colw = lane >> 1;
    const int h    = lane & 1;
#pragma unroll
    for (int r = 0; r < 32; r++)
        sw[32 * r + 2 * (colw ^ (r & 15)) + h] = v[r];
    __syncwarp();

    // ---- exch1 read: LDS.128; thread reads its full 256B region (r = lane) ----
    // float4 k = i3..i6; components (x,y)=(i0 pair @ i2=0), (z,w)=(@ i2=1)
    const float4* swf4 = (const float4*)sw;
    const int m15 = lane & 15;
    u64* vv = v;
#pragma unroll
    for (int k = 0; k < 16; k++) {
        float4 q = swf4[16 * lane + (k ^ m15)];
        vv[2 * k]     = pk(q.x, q.y);   // i2 = 0
        vv[2 * k + 1] = pk(q.z, q.w);   // i2 = 1
    }

    // ---- P2: i2 (bit0), i3..i6 (bits 1..4) ----
    bfly<1>(v, NEG1); bfly<2>(v, NEG1); bfly<4>(v, NEG1);
    bfly<8>(v, NEG1); bfly<16>(v, NEG1);

    // ---- CZ sign + 2^{-5.5}: i9,i10 = lane bits 3,4 -> thread-uniform ----
    {
        const float S  = 0.022097086912079608f;   // 2^{-5.5}
        float sc = ((lane & 24) == 24) ? -S : S;
        u64 sc2 = pk(sc, sc);
#pragma unroll
        for (int r = 0; r < 32; r++) v[r] = pmul(v[r], sc2);
    }
    __syncwarp();   // exch1 reads complete before exch2 writes

    // ---- exch2 write: STS.128 (same layout; r = lane) ----
    float4* swf4w = (float4*)sw;
#pragma unroll
    for (int k = 0; k < 16; k++) {
        float a, b, c, d;
        upk(v[2 * k], a, b); upk(v[2 * k + 1], c, d);
        swf4w[16 * lane + (k ^ m15)] = make_float4(a, b, c, d);
    }
    __syncwarp();

    // ---- exch2 read: LDS.64 (unit (r=i1+2j, col=lane>>1, h=lane&1)) + STG ----
#pragma unroll
    for (int j = 0; j < 16; j++) {
        int r0 = 2 * j, r1 = 2 * j + 1;
        u64 u0 = sw[32 * r0 + 2 * (colw ^ (r0 & 15)) + h];   // i1 = 0
        u64 u1 = sw[32 * r1 + 2 * (colw ^ (r1 & 15)) + h];   // i1 = 1
        float a, b, c, d;
        upk(u0, a, b); upk(u1, c, d);
        op[lane + 32 * j] = make_float4(a, b, c, d);   // (i0,i1) = (x:00,y:10,z:01,w:11)
    }
}

extern "C" void kernel_launch(void* const* d_in, const int* in_sizes, int n_in,
                              void* d_out, int out_size) {
    const float4* in = (const float4*)d_in[0];
    float4* out = (float4*)d_out;
    const int rows = in_sizes[0] / NN;    // 16384
    fwht_cz_kernel<<<rows / 4, 128>>>(in, out);
}